// round 1
// baseline (speedup 1.0000x reference)
#include <cuda_runtime.h>
#include <math.h>

// ---------------- problem constants ----------------
namespace la {
constexpr int DIM    = 1024;
constexpr int NHEADS = 16;
constexpr int HD     = 64;       // head dim
constexpr int NB     = 4;        // batch
constexpr int SEQ    = 4096;
constexpr int ROWS   = NB * SEQ; // 16384
constexpr int CHUNK  = 128;
constexpr int NCHUNK = SEQ / CHUNK; // 32
}

// ---------------- scratch (device globals: allocation-free) ----------------
__device__ float g_qkv[(size_t)la::ROWS * 3 * la::DIM];                       // 201 MB
__device__ float g_attn[(size_t)la::ROWS * la::DIM];                          // 67 MB
__device__ float g_ckv[(size_t)la::NB * la::NHEADS * la::NCHUNK * la::HD * la::HD]; // 33 MB
__device__ float g_cks[(size_t)la::NB * la::NHEADS * la::NCHUNK * la::HD];

// ---------------- SGEMM: C[M,N] = A[M,K] @ B[K,N], all row-major, fp32 -----
// 128x128 block, BK=8, 256 threads, 8x8 per-thread tile.
__global__ __launch_bounds__(256) void sgemm128(const float* __restrict__ A,
                                                const float* __restrict__ Bm,
                                                float* __restrict__ C,
                                                int M, int Nn, int K)
{
    __shared__ float As[8][128];   // transposed A tile
    __shared__ float Bs[8][128];

    const int tid  = threadIdx.x;
    const int cRow = blockIdx.y, cCol = blockIdx.x;

    const float* Ab = A  + (size_t)cRow * 128 * K;
    const float* Bb = Bm + (size_t)cCol * 128;
    float*       Cb = C  + (size_t)cRow * 128 * Nn + (size_t)cCol * 128;

    const int aRow = tid >> 1, aCol = (tid & 1) << 2;
    const int bRow = tid >> 5, bCol = (tid & 31) << 2;
    const int ty = tid >> 4, tx = tid & 15;

    float acc[8][8];
#pragma unroll
    for (int i = 0; i < 8; i++)
#pragma unroll
        for (int j = 0; j < 8; j++) acc[i][j] = 0.f;

    float rM[8], rN[8];
    for (int k0 = 0; k0 < K; k0 += 8) {
        float4 a = *(const float4*)(Ab + (size_t)aRow * K + k0 + aCol);
        As[aCol + 0][aRow] = a.x;
        As[aCol + 1][aRow] = a.y;
        As[aCol + 2][aRow] = a.z;
        As[aCol + 3][aRow] = a.w;
        *(float4*)(&Bs[bRow][bCol]) = *(const float4*)(Bb + (size_t)(k0 + bRow) * Nn + bCol);
        __syncthreads();
#pragma unroll
        for (int kk = 0; kk < 8; kk++) {
#pragma unroll
            for (int i = 0; i < 8; i++) rM[i] = As[kk][ty * 8 + i];
#pragma unroll
            for (int j = 0; j < 8; j++) rN[j] = Bs[kk][tx * 8 + j];
#pragma unroll
            for (int i = 0; i < 8; i++)
#pragma unroll
                for (int j = 0; j < 8; j++) acc[i][j] = fmaf(rM[i], rN[j], acc[i][j]);
        }
        __syncthreads();
    }
#pragma unroll
    for (int i = 0; i < 8; i++)
#pragma unroll
        for (int j = 0; j < 8; j += 4) {
            *(float4*)(Cb + (size_t)(ty * 8 + i) * Nn + tx * 8 + j) =
                make_float4(acc[i][j], acc[i][j + 1], acc[i][j + 2], acc[i][j + 3]);
        }
}

// ---------------- RoPE + elu feature map, in place on q and k --------------
// One warp handles one (row, head, q-or-k): lane j owns the (j, j+32) pair.
__global__ __launch_bounds__(256) void rope_feat()
{
    const int w     = (blockIdx.x << 3) + (threadIdx.x >> 5); // global warp id
    const int lane  = threadIdx.x & 31;
    const int which = w & 1;          // 0 = q, 1 = k
    const int head  = (w >> 1) & 15;
    const int row   = w >> 5;
    const int n     = row & (la::SEQ - 1);

    float* p = g_qkv + (size_t)row * 3072 + which * 1024 + head * 64;
    float x1 = p[lane];
    float x2 = p[lane + 32];

    // match jnp fp32 order: pow -> reciprocal -> n * inv_freq
    float pw   = powf(10000.0f, (float)lane * (1.0f / 32.0f));
    float invf = 1.0f / pw;
    float ang  = (float)n * invf;
    float s, c;
    sincosf(ang, &s, &c);

    float o1 = x1 * c - x2 * s;
    float o2 = x1 * s + x2 * c;
    const float SC = 0.35355339059327373f; // 64^(-1/4)
    o1 *= SC; o2 *= SC;
    o1 = (o1 > 0.f) ? (o1 + 1.0f) : expf(o1); // elu(z)+1
    o2 = (o2 > 0.f) ? (o2 + 1.0f) : expf(o2);
    p[lane]      = o1;
    p[lane + 32] = o2;
}

// ---------------- per-chunk KV outer-product sum + k column sum ------------
__global__ __launch_bounds__(256) void chunk_sums()
{
    extern __shared__ float sm[];
    float* ks = sm;                     // [128][64]
    float* vs = sm + 128 * 64;          // [128][64]

    const int c  = blockIdx.x;
    const int bh = blockIdx.y;
    const int b  = bh >> 4, h = bh & 15;
    const int tid = threadIdx.x;

    const size_t rowbase = (size_t)(b * la::SEQ + c * la::CHUNK) * 3072 + h * 64;
    const float* kg = g_qkv + rowbase + 1024;
    const float* vg = g_qkv + rowbase + 2048;

#pragma unroll
    for (int i = 0; i < 8; i++) {
        int lin = (i * 256 + tid) * 4;
        int t = lin >> 6, col = lin & 63;
        *(float4*)(ks + t * 64 + col) = *(const float4*)(kg + (size_t)t * 3072 + col);
        *(float4*)(vs + t * 64 + col) = *(const float4*)(vg + (size_t)t * 3072 + col);
    }
    __syncthreads();

    const int tx = tid & 15, ty = tid >> 4;
    const int d0 = ty * 4, m0 = tx * 4;
    float acc[4][4] = {};
    for (int t = 0; t < 128; t++) {
        float4 kk = *(const float4*)(ks + t * 64 + d0);
        float4 vv = *(const float4*)(vs + t * 64 + m0);
        float kr[4] = {kk.x, kk.y, kk.z, kk.w};
        float vr[4] = {vv.x, vv.y, vv.z, vv.w};
#pragma unroll
        for (int i = 0; i < 4; i++)
#pragma unroll
            for (int j = 0; j < 4; j++) acc[i][j] = fmaf(kr[i], vr[j], acc[i][j]);
    }
    float* outp = g_ckv + ((size_t)bh * la::NCHUNK + c) * 4096;
#pragma unroll
    for (int i = 0; i < 4; i++)
#pragma unroll
        for (int j = 0; j < 4; j++) outp[(d0 + i) * 64 + m0 + j] = acc[i][j];

    if (tid < 64) {
        float s = 0.f;
        for (int t = 0; t < 128; t++) s += ks[t * 64 + tid];
        g_cks[((size_t)bh * la::NCHUNK + c) * 64 + tid] = s;
    }
}

// ---------------- sequential exclusive prefix over chunks (per b,h) --------
__global__ __launch_bounds__(256) void prefix_scan()
{
    const int bh = blockIdx.x;
    const int tid = threadIdx.x;
    float run[16];
#pragma unroll
    for (int i = 0; i < 16; i++) run[i] = 0.f;
    float runk = 0.f;

    for (int c = 0; c < la::NCHUNK; c++) {
        float* base = g_ckv + ((size_t)bh * la::NCHUNK + c) * 4096;
#pragma unroll
        for (int i = 0; i < 16; i++) {
            int idx = tid + i * 256;
            float t = base[idx];
            base[idx] = run[i];
            run[i] += t;
        }
        if (tid < 64) {
            float* kb = g_cks + ((size_t)bh * la::NCHUNK + c) * 64 + tid;
            float t = *kb;
            *kb = runk;
            runk += t;
        }
    }
}

// ---------------- per-chunk output: intra-causal + inter via KV prefix -----
// smem layout (floats): sQt[64][128] | sU (Kt[64][128] then V[128][64]) |
//                       sS[128][129] | sKV[64][64] | sks[64]
__global__ __launch_bounds__(256) void chunk_out()
{
    extern __shared__ float sm[];
    float* sQt = sm;                 // 8192
    float* sU  = sm + 8192;          // 8192
    float* sS  = sm + 16384;         // 16512
    float* sKV = sm + 16384 + 16512; // 4096
    float* sks = sKV + 4096;         // 64

    const int c  = blockIdx.x;
    const int bh = blockIdx.y;
    const int b  = bh >> 4, h = bh & 15;
    const int tid = threadIdx.x;

    const size_t rowbase = (size_t)(b * la::SEQ + c * la::CHUNK) * 3072 + h * 64;
    const float* qg = g_qkv + rowbase;
    const float* kg = qg + 1024;
    const float* vg = qg + 2048;

    // load Q and K transposed: s[d][t]
#pragma unroll
    for (int i = 0; i < 8; i++) {
        int lin = (i * 256 + tid) * 4;
        int t = lin >> 6, d = lin & 63;
        float4 q4 = *(const float4*)(qg + (size_t)t * 3072 + d);
        sQt[(d + 0) * 128 + t] = q4.x;
        sQt[(d + 1) * 128 + t] = q4.y;
        sQt[(d + 2) * 128 + t] = q4.z;
        sQt[(d + 3) * 128 + t] = q4.w;
        float4 k4 = *(const float4*)(kg + (size_t)t * 3072 + d);
        sU[(d + 0) * 128 + t] = k4.x;
        sU[(d + 1) * 128 + t] = k4.y;
        sU[(d + 2) * 128 + t] = k4.z;
        sU[(d + 3) * 128 + t] = k4.w;
    }
    // KV prefix + ks prefix
    const float* kvg = g_ckv + ((size_t)bh * la::NCHUNK + c) * 4096;
#pragma unroll
    for (int i = 0; i < 4; i++) {
        int lin = (i * 256 + tid) * 4;
        *(float4*)(sKV + lin) = *(const float4*)(kvg + lin);
    }
    if (tid < 64) sks[tid] = g_cks[((size_t)bh * la::NCHUNK + c) * 64 + tid];
    __syncthreads();

    // stage 1: S = Q K^T  (128x128), 8x8 per thread
    {
        const int tx = tid & 15, ty = tid >> 4;
        const int r0 = ty * 8, j0 = tx * 8;
        float acc[8][8];
#pragma unroll
        for (int i = 0; i < 8; i++)
#pragma unroll
            for (int j = 0; j < 8; j++) acc[i][j] = 0.f;
        for (int d = 0; d < 64; d++) {
            float4 qa = *(const float4*)(sQt + d * 128 + r0);
            float4 qb = *(const float4*)(sQt + d * 128 + r0 + 4);
            float4 ka = *(const float4*)(sU + d * 128 + j0);
            float4 kb = *(const float4*)(sU + d * 128 + j0 + 4);
            float qr[8] = {qa.x, qa.y, qa.z, qa.w, qb.x, qb.y, qb.z, qb.w};
            float kr[8] = {ka.x, ka.y, ka.z, ka.w, kb.x, kb.y, kb.z, kb.w};
#pragma unroll
            for (int i = 0; i < 8; i++)
#pragma unroll
                for (int j = 0; j < 8; j++) acc[i][j] = fmaf(qr[i], kr[j], acc[i][j]);
        }
#pragma unroll
        for (int i = 0; i < 8; i++)
#pragma unroll
            for (int j = 0; j < 8; j++) sS[(r0 + i) * 129 + j0 + j] = acc[i][j];
    }
    __syncthreads();

    // overwrite K region with V (row-major [t][64])
#pragma unroll
    for (int i = 0; i < 8; i++) {
        int lin = (i * 256 + tid) * 4;
        int t = lin >> 6, d = lin & 63;
        *(float4*)(sU + t * 64 + d) = *(const float4*)(vg + (size_t)t * 3072 + d);
    }
    __syncthreads();

    // stage 2: out[r][m] = sum_{j<=r} S[r][j] V[j][m] + sum_d Q[r][d] KV[d][m]
    //          denom[r]  = sum_{j<=r} S[r][j] + sum_d Q[r][d] ks[d]
    const int r  = tid >> 1;
    const int m0 = (tid & 1) * 32;
    float out[32];
#pragma unroll
    for (int i = 0; i < 32; i++) out[i] = 0.f;
    float denom = 0.f;

    for (int d = 0; d < 64; d++) {
        float q = sQt[d * 128 + r];
        denom = fmaf(q, sks[d], denom);
        const float4* kvp = (const float4*)(sKV + d * 64 + m0);
#pragma unroll
        for (int i = 0; i < 8; i++) {
            float4 v = kvp[i];
            out[4 * i + 0] = fmaf(q, v.x, out[4 * i + 0]);
            out[4 * i + 1] = fmaf(q, v.y, out[4 * i + 1]);
            out[4 * i + 2] = fmaf(q, v.z, out[4 * i + 2]);
            out[4 * i + 3] = fmaf(q, v.w, out[4 * i + 3]);
        }
    }
    for (int j = 0; j <= r; j++) {
        float s = sS[r * 129 + j];
        denom += s;
        const float4* vp = (const float4*)(sU + j * 64 + m0);
#pragma unroll
        for (int i = 0; i < 8; i++) {
            float4 v = vp[i];
            out[4 * i + 0] = fmaf(s, v.x, out[4 * i + 0]);
            out[4 * i + 1] = fmaf(s, v.y, out[4 * i + 1]);
            out[4 * i + 2] = fmaf(s, v.z, out[4 * i + 2]);
            out[4 * i + 3] = fmaf(s, v.w, out[4 * i + 3]);
        }
    }
    denom = fmaxf(denom, 1e-6f);
    float inv = 1.0f / denom;

    float* og = g_attn + (size_t)(b * la::SEQ + c * la::CHUNK + r) * 1024 + h * 64 + m0;
#pragma unroll
    for (int i = 0; i < 8; i++) {
        *(float4*)(og + 4 * i) = make_float4(out[4 * i + 0] * inv, out[4 * i + 1] * inv,
                                             out[4 * i + 2] * inv, out[4 * i + 3] * inv);
    }
}

// ---------------- launch ----------------
extern "C" void kernel_launch(void* const* d_in, const int* in_sizes, int n_in,
                              void* d_out, int out_size)
{
    const float* x     = (const float*)d_in[0];
    const float* wqkv  = (const float*)d_in[1];
    const float* wout  = (const float*)d_in[2];
    float*       out   = (float*)d_out;

    float *qkv, *attn;
    cudaGetSymbolAddress((void**)&qkv, g_qkv);
    cudaGetSymbolAddress((void**)&attn, g_attn);

    cudaFuncSetAttribute(chunk_sums, cudaFuncAttributeMaxDynamicSharedMemorySize, 65536);
    cudaFuncSetAttribute(chunk_out,  cudaFuncAttributeMaxDynamicSharedMemorySize, 148224);

    // 1) qkv = x @ w_qkv
    dim3 g1(3 * la::DIM / 128, la::ROWS / 128);
    sgemm128<<<g1, 256>>>(x, wqkv, qkv, la::ROWS, 3 * la::DIM, la::DIM);

    // 2) RoPE + elu featurization (in place on q,k)
    rope_feat<<<la::ROWS * la::NHEADS * 2 / 8, 256>>>();

    // 3) per-chunk KV sums
    dim3 g3(la::NCHUNK, la::NB * la::NHEADS);
    chunk_sums<<<g3, 256, 65536>>>();

    // 4) exclusive prefix over chunks
    prefix_scan<<<la::NB * la::NHEADS, 256>>>();

    // 5) per-chunk outputs
    chunk_out<<<g3, 256, 148224>>>();

    // 6) out = attn @ w_out
    dim3 g6(la::DIM / 128, la::ROWS / 128);
    sgemm128<<<g6, 256>>>(attn, wout, out, la::ROWS, la::DIM, la::DIM);
}

// round 3
// speedup vs baseline: 3.8402x; 3.8402x over previous
#include <cuda_runtime.h>
#include <math.h>
#include <stdint.h>

// ---------------- problem constants ----------------
namespace la {
constexpr int DIM    = 1024;
constexpr int NHEADS = 16;
constexpr int HD     = 64;
constexpr int NB     = 4;
constexpr int SEQ    = 4096;
constexpr int ROWS   = NB * SEQ; // 16384
constexpr int CHUNK  = 128;
constexpr int NCHUNK = SEQ / CHUNK; // 32
}

// ---------------- scratch (device globals: allocation-free) ----------------
__device__ float g_qkv[(size_t)la::ROWS * 3 * la::DIM];
__device__ float g_attn[(size_t)la::ROWS * la::DIM];
__device__ float g_ckv[(size_t)la::NB * la::NHEADS * la::NCHUNK * la::HD * la::HD];
__device__ float g_cks[(size_t)la::NB * la::NHEADS * la::NCHUNK * la::HD];
__device__ float g_wT[3072 * 1024 + 1024 * 1024]; // transposed weights

// ---------------- helpers ----------------
__device__ __forceinline__ uint32_t cvt_tf32(float f) {
    uint32_t u;
    asm("cvt.rna.tf32.f32 %0, %1;" : "=r"(u) : "f"(f));
    return u;
}

#define MMA_TF32(c, a, b0, b1)                                              \
    asm volatile("mma.sync.aligned.m16n8k8.row.col.f32.tf32.tf32.f32 "      \
                 "{%0,%1,%2,%3},{%4,%5,%6,%7},{%8,%9},{%0,%1,%2,%3};"       \
                 : "+f"((c)[0]), "+f"((c)[1]), "+f"((c)[2]), "+f"((c)[3])   \
                 : "r"((a)[0]), "r"((a)[1]), "r"((a)[2]), "r"((a)[3]),      \
                   "r"(b0), "r"(b1))

// ============ tensor-core tf32 GEMM: C[M,N] = A[M,K] @ Bt[N,K]^T ==========
// 128x128 CTA tile, BK=32, 256 threads (8 warps), warp tile 32x64.
// smem: double-buffered A/B tiles, [row 0..127][k 0..31] with stride 36.
static constexpr int GM_STRIDE = 36;
static constexpr int GM_TILE   = 128 * GM_STRIDE;          // floats per tile
static constexpr int GM_SMEM   = 4 * GM_TILE * 4;          // bytes = 73728

__global__ __launch_bounds__(256, 2) void gemm_mma(const float* __restrict__ A,
                                                   const float* __restrict__ Bt,
                                                   float* __restrict__ C,
                                                   int M, int N, int K)
{
    extern __shared__ float smf[];
    float* sA[2] = { smf,               smf + 2 * GM_TILE };
    float* sB[2] = { smf + GM_TILE,     smf + 3 * GM_TILE };

    const int tid  = threadIdx.x;
    const int wid  = tid >> 5, lane = tid & 31;
    const int g    = lane >> 2, tig = lane & 3;
    const int wm   = (wid & 3) * 32, wn = (wid >> 2) * 64;

    const float* Ab = A  + (size_t)blockIdx.y * 128 * K;
    const float* Bb = Bt + (size_t)blockIdx.x * 128 * K;

    float acc[2][8][4];
#pragma unroll
    for (int mt = 0; mt < 2; mt++)
#pragma unroll
        for (int nt = 0; nt < 8; nt++)
#pragma unroll
            for (int i = 0; i < 4; i++) acc[mt][nt][i] = 0.f;

    float4 ra[4], rb[4];

    auto ldg = [&](int kc) {
#pragma unroll
        for (int i = 0; i < 4; i++) {
            int lin = i * 256 + tid;
            int r = lin >> 3, q = (lin & 7) << 2;
            ra[i] = *(const float4*)(Ab + (size_t)r * K + kc * 32 + q);
            rb[i] = *(const float4*)(Bb + (size_t)r * K + kc * 32 + q);
        }
    };
    auto sts = [&](int buf) {
#pragma unroll
        for (int i = 0; i < 4; i++) {
            int lin = i * 256 + tid;
            int r = lin >> 3, q = (lin & 7) << 2;
            uint4 ua = { cvt_tf32(ra[i].x), cvt_tf32(ra[i].y),
                         cvt_tf32(ra[i].z), cvt_tf32(ra[i].w) };
            *(uint4*)(sA[buf] + r * GM_STRIDE + q) = ua;
            uint4 ub = { cvt_tf32(rb[i].x), cvt_tf32(rb[i].y),
                         cvt_tf32(rb[i].z), cvt_tf32(rb[i].w) };
            *(uint4*)(sB[buf] + r * GM_STRIDE + q) = ub;
        }
    };
    auto compute = [&](int buf) {
        const uint32_t* uA = (const uint32_t*)sA[buf];
        const uint32_t* uB = (const uint32_t*)sB[buf];
#pragma unroll
        for (int ks = 0; ks < 4; ks++) {
            const int kb = ks * 8;
            uint32_t af[2][4];
#pragma unroll
            for (int mt = 0; mt < 2; mt++) {
                int r = wm + mt * 16 + g;
                af[mt][0] = uA[r * GM_STRIDE + kb + tig];
                af[mt][1] = uA[(r + 8) * GM_STRIDE + kb + tig];
                af[mt][2] = uA[r * GM_STRIDE + kb + tig + 4];
                af[mt][3] = uA[(r + 8) * GM_STRIDE + kb + tig + 4];
            }
#pragma unroll
            for (int nt = 0; nt < 8; nt++) {
                int n = wn + nt * 8 + g;
                uint32_t b0 = uB[n * GM_STRIDE + kb + tig];
                uint32_t b1 = uB[n * GM_STRIDE + kb + tig + 4];
                MMA_TF32(acc[0][nt], af[0], b0, b1);
                MMA_TF32(acc[1][nt], af[1], b0, b1);
            }
        }
    };

    ldg(0);
    sts(0);
    __syncthreads();
    const int KC = K >> 5;
    for (int kc = 0; kc < KC; kc++) {
        const int cur = kc & 1;
        if (kc + 1 < KC) ldg(kc + 1);
        compute(cur);
        if (kc + 1 < KC) sts(cur ^ 1);
        __syncthreads();
    }

    // epilogue: direct float2 stores
#pragma unroll
    for (int mt = 0; mt < 2; mt++) {
        const int row0 = blockIdx.y * 128 + wm + mt * 16 + g;
#pragma unroll
        for (int nt = 0; nt < 8; nt++) {
            const int col = blockIdx.x * 128 + wn + nt * 8 + tig * 2;
            *(float2*)(C + (size_t)row0 * N + col) =
                make_float2(acc[mt][nt][0], acc[mt][nt][1]);
            *(float2*)(C + (size_t)(row0 + 8) * N + col) =
                make_float2(acc[mt][nt][2], acc[mt][nt][3]);
        }
    }
}

// ---------------- weight transpose: dst[Ccols][R] = src[R][Ccols]^T --------
__global__ __launch_bounds__(256) void transpose_w(const float* __restrict__ src,
                                                   float* __restrict__ dst,
                                                   int R, int Ccols)
{
    __shared__ float t[32][33];
    const int bx = blockIdx.x * 32, by = blockIdx.y * 32;
    const int x = threadIdx.x & 31, y = threadIdx.x >> 5; // 32x8
#pragma unroll
    for (int i = 0; i < 32; i += 8)
        t[y + i][x] = src[(size_t)(by + y + i) * Ccols + bx + x];
    __syncthreads();
#pragma unroll
    for (int i = 0; i < 32; i += 8)
        dst[(size_t)(bx + y + i) * R + by + x] = t[x][y + i];
}

// ---------------- RoPE + elu feature map ----------------------------------
__global__ __launch_bounds__(256) void rope_feat()
{
    const int w     = (blockIdx.x << 3) + (threadIdx.x >> 5);
    const int lane  = threadIdx.x & 31;
    const int which = w & 1;
    const int head  = (w >> 1) & 15;
    const int row   = w >> 5;
    const int n     = row & (la::SEQ - 1);

    float* p = g_qkv + (size_t)row * 3072 + which * 1024 + head * 64;
    float x1 = p[lane];
    float x2 = p[lane + 32];

    float pw   = powf(10000.0f, (float)lane * (1.0f / 32.0f));
    float invf = 1.0f / pw;
    float ang  = (float)n * invf;
    float s, c;
    sincosf(ang, &s, &c);

    float o1 = x1 * c - x2 * s;
    float o2 = x1 * s + x2 * c;
    const float SC = 0.35355339059327373f;
    o1 *= SC; o2 *= SC;
    o1 = (o1 > 0.f) ? (o1 + 1.0f) : expf(o1);
    o2 = (o2 > 0.f) ? (o2 + 1.0f) : expf(o2);
    p[lane]      = o1;
    p[lane + 32] = o2;
}

// ---------------- per-chunk KV outer-product sum + k column sum ------------
__global__ __launch_bounds__(256) void chunk_sums()
{
    extern __shared__ float sm[];
    float* ks = sm;
    float* vs = sm + 128 * 64;

    const int c  = blockIdx.x;
    const int bh = blockIdx.y;
    const int b  = bh >> 4, h = bh & 15;
    const int tid = threadIdx.x;

    const size_t rowbase = (size_t)(b * la::SEQ + c * la::CHUNK) * 3072 + h * 64;
    const float* kg = g_qkv + rowbase + 1024;
    const float* vg = g_qkv + rowbase + 2048;

#pragma unroll
    for (int i = 0; i < 8; i++) {
        int lin = (i * 256 + tid) * 4;
        int t = lin >> 6, col = lin & 63;
        *(float4*)(ks + t * 64 + col) = *(const float4*)(kg + (size_t)t * 3072 + col);
        *(float4*)(vs + t * 64 + col) = *(const float4*)(vg + (size_t)t * 3072 + col);
    }
    __syncthreads();

    const int tx = tid & 15, ty = tid >> 4;
    const int d0 = ty * 4, m0 = tx * 4;
    float acc[4][4] = {};
    for (int t = 0; t < 128; t++) {
        float4 kk = *(const float4*)(ks + t * 64 + d0);
        float4 vv = *(const float4*)(vs + t * 64 + m0);
        float kr[4] = {kk.x, kk.y, kk.z, kk.w};
        float vr[4] = {vv.x, vv.y, vv.z, vv.w};
#pragma unroll
        for (int i = 0; i < 4; i++)
#pragma unroll
            for (int j = 0; j < 4; j++) acc[i][j] = fmaf(kr[i], vr[j], acc[i][j]);
    }
    float* outp = g_ckv + ((size_t)bh * la::NCHUNK + c) * 4096;
#pragma unroll
    for (int i = 0; i < 4; i++)
#pragma unroll
        for (int j = 0; j < 4; j++) outp[(d0 + i) * 64 + m0 + j] = acc[i][j];

    if (tid < 64) {
        float s = 0.f;
        for (int t = 0; t < 128; t++) s += ks[t * 64 + tid];
        g_cks[((size_t)bh * la::NCHUNK + c) * 64 + tid] = s;
    }
}

// ---------------- exclusive prefix over chunks: register-prefetched --------
__global__ __launch_bounds__(256) void prefix_scan()
{
    const int bh  = blockIdx.x;
    const int seg = blockIdx.y;   // 8 segments of 512 floats (256 float2)
    const int tid = threadIdx.x;

    float2* base = (float2*)(g_ckv + (size_t)bh * la::NCHUNK * 4096) + seg * 256 + tid;
    float2 vals[la::NCHUNK];
#pragma unroll
    for (int c = 0; c < la::NCHUNK; c++) vals[c] = base[c * 2048];
    float2 run = make_float2(0.f, 0.f);
#pragma unroll
    for (int c = 0; c < la::NCHUNK; c++) {
        float2 t = vals[c];
        vals[c] = run;
        run.x += t.x; run.y += t.y;
    }
#pragma unroll
    for (int c = 0; c < la::NCHUNK; c++) base[c * 2048] = vals[c];

    if (seg == 0 && tid < 64) {
        float* kb = g_cks + (size_t)bh * la::NCHUNK * 64 + tid;
        float kv[la::NCHUNK];
#pragma unroll
        for (int c = 0; c < la::NCHUNK; c++) kv[c] = kb[c * 64];
        float r = 0.f;
#pragma unroll
        for (int c = 0; c < la::NCHUNK; c++) { float t = kv[c]; kv[c] = r; r += t; }
#pragma unroll
        for (int c = 0; c < la::NCHUNK; c++) kb[c * 64] = kv[c];
    }
}

// ---------------- per-chunk output: intra-causal + inter via KV prefix -----
__global__ __launch_bounds__(256) void chunk_out()
{
    extern __shared__ float sm[];
    float* sQt = sm;
    float* sU  = sm + 8192;
    float* sS  = sm + 16384;
    float* sKV = sm + 16384 + 16512;
    float* sks = sKV + 4096;

    const int c  = blockIdx.x;
    const int bh = blockIdx.y;
    const int b  = bh >> 4, h = bh & 15;
    const int tid = threadIdx.x;

    const size_t rowbase = (size_t)(b * la::SEQ + c * la::CHUNK) * 3072 + h * 64;
    const float* qg = g_qkv + rowbase;
    const float* kg = qg + 1024;
    const float* vg = qg + 2048;

#pragma unroll
    for (int i = 0; i < 8; i++) {
        int lin = (i * 256 + tid) * 4;
        int t = lin >> 6, d = lin & 63;
        float4 q4 = *(const float4*)(qg + (size_t)t * 3072 + d);
        sQt[(d + 0) * 128 + t] = q4.x;
        sQt[(d + 1) * 128 + t] = q4.y;
        sQt[(d + 2) * 128 + t] = q4.z;
        sQt[(d + 3) * 128 + t] = q4.w;
        float4 k4 = *(const float4*)(kg + (size_t)t * 3072 + d);
        sU[(d + 0) * 128 + t] = k4.x;
        sU[(d + 1) * 128 + t] = k4.y;
        sU[(d + 2) * 128 + t] = k4.z;
        sU[(d + 3) * 128 + t] = k4.w;
    }
    const float* kvg = g_ckv + ((size_t)bh * la::NCHUNK + c) * 4096;
#pragma unroll
    for (int i = 0; i < 4; i++) {
        int lin = (i * 256 + tid) * 4;
        *(float4*)(sKV + lin) = *(const float4*)(kvg + lin);
    }
    if (tid < 64) sks[tid] = g_cks[((size_t)bh * la::NCHUNK + c) * 64 + tid];
    __syncthreads();

    {
        const int tx = tid & 15, ty = tid >> 4;
        const int r0 = ty * 8, j0 = tx * 8;
        float acc[8][8];
#pragma unroll
        for (int i = 0; i < 8; i++)
#pragma unroll
            for (int j = 0; j < 8; j++) acc[i][j] = 0.f;
        for (int d = 0; d < 64; d++) {
            float4 qa = *(const float4*)(sQt + d * 128 + r0);
            float4 qb = *(const float4*)(sQt + d * 128 + r0 + 4);
            float4 ka = *(const float4*)(sU + d * 128 + j0);
            float4 kb = *(const float4*)(sU + d * 128 + j0 + 4);
            float qr[8] = {qa.x, qa.y, qa.z, qa.w, qb.x, qb.y, qb.z, qb.w};
            float kr[8] = {ka.x, ka.y, ka.z, ka.w, kb.x, kb.y, kb.z, kb.w};
#pragma unroll
            for (int i = 0; i < 8; i++)
#pragma unroll
                for (int j = 0; j < 8; j++) acc[i][j] = fmaf(qr[i], kr[j], acc[i][j]);
        }
#pragma unroll
        for (int i = 0; i < 8; i++)
#pragma unroll
            for (int j = 0; j < 8; j++) sS[(r0 + i) * 129 + j0 + j] = acc[i][j];
    }
    __syncthreads();

#pragma unroll
    for (int i = 0; i < 8; i++) {
        int lin = (i * 256 + tid) * 4;
        int t = lin >> 6, d = lin & 63;
        *(float4*)(sU + t * 64 + d) = *(const float4*)(vg + (size_t)t * 3072 + d);
    }
    __syncthreads();

    const int r  = tid >> 1;
    const int m0 = (tid & 1) * 32;
    float out[32];
#pragma unroll
    for (int i = 0; i < 32; i++) out[i] = 0.f;
    float denom = 0.f;

    for (int d = 0; d < 64; d++) {
        float q = sQt[d * 128 + r];
        denom = fmaf(q, sks[d], denom);
        const float4* kvp = (const float4*)(sKV + d * 64 + m0);
#pragma unroll
        for (int i = 0; i < 8; i++) {
            float4 v = kvp[i];
            out[4 * i + 0] = fmaf(q, v.x, out[4 * i + 0]);
            out[4 * i + 1] = fmaf(q, v.y, out[4 * i + 1]);
            out[4 * i + 2] = fmaf(q, v.z, out[4 * i + 2]);
            out[4 * i + 3] = fmaf(q, v.w, out[4 * i + 3]);
        }
    }
    for (int j = 0; j <= r; j++) {
        float s = sS[r * 129 + j];
        denom += s;
        const float4* vp = (const float4*)(sU + j * 64 + m0);
#pragma unroll
        for (int i = 0; i < 8; i++) {
            float4 v = vp[i];
            out[4 * i + 0] = fmaf(s, v.x, out[4 * i + 0]);
            out[4 * i + 1] = fmaf(s, v.y, out[4 * i + 1]);
            out[4 * i + 2] = fmaf(s, v.z, out[4 * i + 2]);
            out[4 * i + 3] = fmaf(s, v.w, out[4 * i + 3]);
        }
    }
    denom = fmaxf(denom, 1e-6f);
    float inv = 1.0f / denom;

    float* og = g_attn + (size_t)(b * la::SEQ + c * la::CHUNK + r) * 1024 + h * 64 + m0;
#pragma unroll
    for (int i = 0; i < 8; i++) {
        *(float4*)(og + 4 * i) = make_float4(out[4 * i + 0] * inv, out[4 * i + 1] * inv,
                                             out[4 * i + 2] * inv, out[4 * i + 3] * inv);
    }
}

// ---------------- launch ----------------
extern "C" void kernel_launch(void* const* d_in, const int* in_sizes, int n_in,
                              void* d_out, int out_size)
{
    const float* x    = (const float*)d_in[0];
    const float* wqkv = (const float*)d_in[1];
    const float* wout = (const float*)d_in[2];
    float*       out  = (float*)d_out;

    float *qkv, *attn, *wT;
    cudaGetSymbolAddress((void**)&qkv, g_qkv);
    cudaGetSymbolAddress((void**)&attn, g_attn);
    cudaGetSymbolAddress((void**)&wT, g_wT);
    float* wqkvT = wT;
    float* woutT = wT + 3072 * 1024;

    cudaFuncSetAttribute(gemm_mma,   cudaFuncAttributeMaxDynamicSharedMemorySize, GM_SMEM);
    cudaFuncSetAttribute(chunk_sums, cudaFuncAttributeMaxDynamicSharedMemorySize, 65536);
    cudaFuncSetAttribute(chunk_out,  cudaFuncAttributeMaxDynamicSharedMemorySize, 148224);

    // 0) transpose weights -> [N][K]
    transpose_w<<<dim3(3072 / 32, 1024 / 32), 256>>>(wqkv, wqkvT, 1024, 3072);
    transpose_w<<<dim3(1024 / 32, 1024 / 32), 256>>>(wout, woutT, 1024, 1024);

    // 1) qkv = x @ w_qkv   (mma.sync tf32)
    gemm_mma<<<dim3(3072 / 128, la::ROWS / 128), 256, GM_SMEM>>>(x, wqkvT, qkv,
                                                                 la::ROWS, 3072, 1024);

    // 2) RoPE + elu featurization
    rope_feat<<<la::ROWS * la::NHEADS * 2 / 8, 256>>>();

    // 3) per-chunk KV sums
    dim3 g3(la::NCHUNK, la::NB * la::NHEADS);
    chunk_sums<<<g3, 256, 65536>>>();

    // 4) exclusive prefix over chunks
    prefix_scan<<<dim3(la::NB * la::NHEADS, 8), 256>>>();

    // 5) per-chunk outputs
    chunk_out<<<g3, 256, 148224>>>();

    // 6) out = attn @ w_out  (mma.sync tf32)
    gemm_mma<<<dim3(1024 / 128, la::ROWS / 128), 256, GM_SMEM>>>(attn, woutT, out,
                                                                 la::ROWS, 1024, 1024);
}

// round 4
// speedup vs baseline: 4.7265x; 1.2308x over previous
#include <cuda_runtime.h>
#include <math.h>
#include <stdint.h>

// ---------------- problem constants ----------------
namespace la {
constexpr int DIM    = 1024;
constexpr int NHEADS = 16;
constexpr int HD     = 64;
constexpr int NB     = 4;
constexpr int SEQ    = 4096;
constexpr int ROWS   = NB * SEQ; // 16384
constexpr int CHUNK  = 128;
constexpr int NCHUNK = SEQ / CHUNK; // 32
}

// ---------------- scratch (device globals: allocation-free) ----------------
__device__ float g_qkv[(size_t)la::ROWS * 3 * la::DIM];
__device__ float g_attn[(size_t)la::ROWS * la::DIM];
__device__ float g_ckv[(size_t)la::NB * la::NHEADS * la::NCHUNK * la::HD * la::HD];
__device__ float g_cks[(size_t)la::NB * la::NHEADS * la::NCHUNK * la::HD];
__device__ float g_wT[3072 * 1024 + 1024 * 1024];
__device__ float2 g_lut[la::SEQ * 32];   // cos/sin per (n, lane)

// ---------------- helpers ----------------
__device__ __forceinline__ uint32_t cvt_tf32(float f) {
    uint32_t u;
    asm("cvt.rna.tf32.f32 %0, %1;" : "=r"(u) : "f"(f));
    return u;
}
__device__ __forceinline__ float tf32f(float f) { return __uint_as_float(cvt_tf32(f)); }

#define MMA_TF32(c, a, b0, b1)                                              \
    asm volatile("mma.sync.aligned.m16n8k8.row.col.f32.tf32.tf32.f32 "      \
                 "{%0,%1,%2,%3},{%4,%5,%6,%7},{%8,%9},{%0,%1,%2,%3};"       \
                 : "+f"((c)[0]), "+f"((c)[1]), "+f"((c)[2]), "+f"((c)[3])   \
                 : "r"((a)[0]), "r"((a)[1]), "r"((a)[2]), "r"((a)[3]),      \
                   "r"(b0), "r"(b1))

__device__ __forceinline__ float elu1(float z) {
    return (z > 0.f) ? (z + 1.0f) : expf(z);
}
constexpr float ROPE_SC = 0.35355339059327373f; // 64^(-1/4)

// ============ rope LUT build ==============================================
__global__ void rope_lut_build()
{
    const int n = blockIdx.x, lane = threadIdx.x;
    float pw   = powf(10000.0f, (float)lane * (1.0f / 32.0f));
    float invf = 1.0f / pw;
    float ang  = (float)n * invf;
    float s, c;
    sincosf(ang, &s, &c);
    g_lut[n * 32 + lane] = make_float2(c, s);
}

// ============ tensor-core tf32 GEMM: C[M,N] = A[M,K] @ Bt[N,K]^T ==========
static constexpr int GM_STRIDE = 36;
static constexpr int GM_TILE   = 128 * GM_STRIDE;
static constexpr int GM_SMEM   = 4 * GM_TILE * 4; // 73728 B

__global__ __launch_bounds__(256, 2) void gemm_mma(const float* __restrict__ A,
                                                   const float* __restrict__ Bt,
                                                   float* __restrict__ C,
                                                   int M, int N, int K)
{
    extern __shared__ float smf[];
    float* sA[2] = { smf,           smf + 2 * GM_TILE };
    float* sB[2] = { smf + GM_TILE, smf + 3 * GM_TILE };

    const int tid  = threadIdx.x;
    const int wid  = tid >> 5, lane = tid & 31;
    const int g    = lane >> 2, tig = lane & 3;
    const int wm   = (wid & 3) * 32, wn = (wid >> 2) * 64;

    const float* Ab = A  + (size_t)blockIdx.y * 128 * K;
    const float* Bb = Bt + (size_t)blockIdx.x * 128 * K;

    float acc[2][8][4];
#pragma unroll
    for (int mt = 0; mt < 2; mt++)
#pragma unroll
        for (int nt = 0; nt < 8; nt++)
#pragma unroll
            for (int i = 0; i < 4; i++) acc[mt][nt][i] = 0.f;

    float4 ra[4], rb[4];
    auto ldg = [&](int kc) {
#pragma unroll
        for (int i = 0; i < 4; i++) {
            int lin = i * 256 + tid;
            int r = lin >> 3, q = (lin & 7) << 2;
            ra[i] = *(const float4*)(Ab + (size_t)r * K + kc * 32 + q);
            rb[i] = *(const float4*)(Bb + (size_t)r * K + kc * 32 + q);
        }
    };
    auto sts = [&](int buf) {
#pragma unroll
        for (int i = 0; i < 4; i++) {
            int lin = i * 256 + tid;
            int r = lin >> 3, q = (lin & 7) << 2;
            uint4 ua = { cvt_tf32(ra[i].x), cvt_tf32(ra[i].y),
                         cvt_tf32(ra[i].z), cvt_tf32(ra[i].w) };
            *(uint4*)(sA[buf] + r * GM_STRIDE + q) = ua;
            uint4 ub = { cvt_tf32(rb[i].x), cvt_tf32(rb[i].y),
                         cvt_tf32(rb[i].z), cvt_tf32(rb[i].w) };
            *(uint4*)(sB[buf] + r * GM_STRIDE + q) = ub;
        }
    };
    auto compute = [&](int buf) {
        const uint32_t* uA = (const uint32_t*)sA[buf];
        const uint32_t* uB = (const uint32_t*)sB[buf];
#pragma unroll
        for (int ks = 0; ks < 4; ks++) {
            const int kb = ks * 8;
            uint32_t af[2][4];
#pragma unroll
            for (int mt = 0; mt < 2; mt++) {
                int r = wm + mt * 16 + g;
                af[mt][0] = uA[r * GM_STRIDE + kb + tig];
                af[mt][1] = uA[(r + 8) * GM_STRIDE + kb + tig];
                af[mt][2] = uA[r * GM_STRIDE + kb + tig + 4];
                af[mt][3] = uA[(r + 8) * GM_STRIDE + kb + tig + 4];
            }
#pragma unroll
            for (int nt = 0; nt < 8; nt++) {
                int n = wn + nt * 8 + g;
                uint32_t b0 = uB[n * GM_STRIDE + kb + tig];
                uint32_t b1 = uB[n * GM_STRIDE + kb + tig + 4];
                MMA_TF32(acc[0][nt], af[0], b0, b1);
                MMA_TF32(acc[1][nt], af[1], b0, b1);
            }
        }
    };

    ldg(0);
    sts(0);
    __syncthreads();
    const int KC = K >> 5;
    for (int kc = 0; kc < KC; kc++) {
        const int cur = kc & 1;
        if (kc + 1 < KC) ldg(kc + 1);
        compute(cur);
        if (kc + 1 < KC) sts(cur ^ 1);
        __syncthreads();
    }

#pragma unroll
    for (int mt = 0; mt < 2; mt++) {
        const int row0 = blockIdx.y * 128 + wm + mt * 16 + g;
#pragma unroll
        for (int nt = 0; nt < 8; nt++) {
            const int col = blockIdx.x * 128 + wn + nt * 8 + tig * 2;
            *(float2*)(C + (size_t)row0 * N + col) =
                make_float2(acc[mt][nt][0], acc[mt][nt][1]);
            *(float2*)(C + (size_t)(row0 + 8) * N + col) =
                make_float2(acc[mt][nt][2], acc[mt][nt][3]);
        }
    }
}

// ---------------- weight transpose ----------------------------------------
__global__ __launch_bounds__(256) void transpose_w(const float* __restrict__ src,
                                                   float* __restrict__ dst,
                                                   int R, int Ccols)
{
    __shared__ float t[32][33];
    const int bx = blockIdx.x * 32, by = blockIdx.y * 32;
    const int x = threadIdx.x & 31, y = threadIdx.x >> 5;
#pragma unroll
    for (int i = 0; i < 32; i += 8)
        t[y + i][x] = src[(size_t)(by + y + i) * Ccols + bx + x];
    __syncthreads();
#pragma unroll
    for (int i = 0; i < 32; i += 8)
        dst[(size_t)(bx + y + i) * R + by + x] = t[x][y + i];
}

// ============ chunk_sums: KV_c = K^T @ V (mma), ks = colsum(K) ============
// smem: sKT [64][132] @0 | sVT [64][132] @8448   (floats)  total 67584 B
static constexpr int CS_SMEM = 16896 * 4;

__global__ __launch_bounds__(256) void chunk_sums()
{
    extern __shared__ float sm[];
    float* sKT = sm;          // [d][t] featurized, tf32-rounded
    float* sVT = sm + 8448;   // [m][t] tf32-rounded

    const int c  = blockIdx.x;
    const int bh = blockIdx.y;
    const int b  = bh >> 4, h = bh & 15;
    const int tid = threadIdx.x;
    const int wid = tid >> 5, lane = tid & 31;
    const int g = lane >> 2, tig = lane & 3;

    const size_t rowbase = (size_t)(b * la::SEQ + c * la::CHUNK) * 3072 + h * 64;
    const float* kg = g_qkv + rowbase + 1024;
    const float* vg = g_qkv + rowbase + 2048;

    // stage K featurized & transposed
#pragma unroll
    for (int i = 0; i < 4; i++) {
        int idx = i * 256 + tid;
        int t = idx >> 3, d0 = (idx & 7) << 2;
        int n = c * la::CHUNK + t;
        float4 ka = *(const float4*)(kg + (size_t)t * 3072 + d0);
        float4 kb = *(const float4*)(kg + (size_t)t * 3072 + d0 + 32);
        float k1[4] = {ka.x, ka.y, ka.z, ka.w};
        float k2[4] = {kb.x, kb.y, kb.z, kb.w};
#pragma unroll
        for (int j = 0; j < 4; j++) {
            float2 cs = g_lut[n * 32 + d0 + j];
            float o1 = (k1[j] * cs.x - k2[j] * cs.y) * ROPE_SC;
            float o2 = (k1[j] * cs.y + k2[j] * cs.x) * ROPE_SC;
            sKT[(d0 + j) * 132 + t]      = tf32f(elu1(o1));
            sKT[(d0 + 32 + j) * 132 + t] = tf32f(elu1(o2));
        }
    }
    // stage V transposed
#pragma unroll
    for (int i = 0; i < 8; i++) {
        int idx = i * 256 + tid;
        int t = idx >> 4, m0 = (idx & 15) << 2;
        float4 v4 = *(const float4*)(vg + (size_t)t * 3072 + m0);
        sVT[(m0 + 0) * 132 + t] = tf32f(v4.x);
        sVT[(m0 + 1) * 132 + t] = tf32f(v4.y);
        sVT[(m0 + 2) * 132 + t] = tf32f(v4.z);
        sVT[(m0 + 3) * 132 + t] = tf32f(v4.w);
    }
    __syncthreads();

    // KV[d][m] = sum_t K[t][d] V[t][m]; warp tile 16x32
    const int wm = (wid & 3) * 16, wn = (wid >> 2) * 32;
    const uint32_t* uK = (const uint32_t*)sKT;
    const uint32_t* uV = (const uint32_t*)sVT;
    float acc[4][4];
#pragma unroll
    for (int nt = 0; nt < 4; nt++)
#pragma unroll
        for (int i = 0; i < 4; i++) acc[nt][i] = 0.f;

#pragma unroll
    for (int ks = 0; ks < 16; ks++) {
        const int kb = ks * 8;
        uint32_t af[4];
        af[0] = uK[(wm + g) * 132 + kb + tig];
        af[1] = uK[(wm + g + 8) * 132 + kb + tig];
        af[2] = uK[(wm + g) * 132 + kb + tig + 4];
        af[3] = uK[(wm + g + 8) * 132 + kb + tig + 4];
#pragma unroll
        for (int nt = 0; nt < 4; nt++) {
            int n = wn + nt * 8 + g;
            uint32_t b0 = uV[n * 132 + kb + tig];
            uint32_t b1 = uV[n * 132 + kb + tig + 4];
            MMA_TF32(acc[nt], af, b0, b1);
        }
    }
    float* outp = g_ckv + ((size_t)bh * la::NCHUNK + c) * 4096;
#pragma unroll
    for (int nt = 0; nt < 4; nt++) {
        int d = wm + g, m = wn + nt * 8 + tig * 2;
        *(float2*)(outp + d * 64 + m)       = make_float2(acc[nt][0], acc[nt][1]);
        *(float2*)(outp + (d + 8) * 64 + m) = make_float2(acc[nt][2], acc[nt][3]);
    }
    // ks: column sums of featurized K
    if (tid < 64) {
        float s = 0.f;
        for (int t = 0; t < 128; t++) s += sKT[tid * 132 + t];
        g_cks[((size_t)bh * la::NCHUNK + c) * 64 + tid] = s;
    }
}

// ---------------- exclusive prefix over chunks -----------------------------
__global__ __launch_bounds__(256) void prefix_scan()
{
    const int bh  = blockIdx.x;
    const int seg = blockIdx.y;
    const int tid = threadIdx.x;

    float2* base = (float2*)(g_ckv + (size_t)bh * la::NCHUNK * 4096) + seg * 256 + tid;
    float2 vals[la::NCHUNK];
#pragma unroll
    for (int c = 0; c < la::NCHUNK; c++) vals[c] = base[c * 2048];
    float2 run = make_float2(0.f, 0.f);
#pragma unroll
    for (int c = 0; c < la::NCHUNK; c++) {
        float2 t = vals[c];
        vals[c] = run;
        run.x += t.x; run.y += t.y;
    }
#pragma unroll
    for (int c = 0; c < la::NCHUNK; c++) base[c * 2048] = vals[c];

    if (seg == 0 && tid < 64) {
        float* kb = g_cks + (size_t)bh * la::NCHUNK * 64 + tid;
        float kv[la::NCHUNK];
#pragma unroll
        for (int c = 0; c < la::NCHUNK; c++) kv[c] = kb[c * 64];
        float r = 0.f;
#pragma unroll
        for (int c = 0; c < la::NCHUNK; c++) { float t = kv[c]; kv[c] = r; r += t; }
#pragma unroll
        for (int c = 0; c < la::NCHUNK; c++) kb[c * 64] = kv[c];
    }
}

// ============ chunk_out: mma-based intra + inter ==========================
// smem floats: sQ[128][68]@0 | sK[128][68]@8704 (reused as sVT[64][132]) |
//              sS[128][132]@17408 | sKVT[64][68]@34304 | sks[64]@38656 |
//              sden[128]@38720  -> 38848 floats = 155392 B
static constexpr int CO_SMEM = 38848 * 4;

__global__ __launch_bounds__(256) void chunk_out()
{
    extern __shared__ float sm[];
    float* sQ   = sm;             // [r][d]  featurized q, tf32
    float* sK   = sm + 8704;      // [t][d]  featurized k, tf32  (later sVT)
    float* sVT  = sm + 8704;      // [m][t]  v^T, tf32 (stage2)
    float* sS   = sm + 17408;     // [r][j]  masked S, tf32
    float* sKVT = sm + 34304;     // [m][d]  KV^T, tf32
    float* sks  = sm + 38656;     // [64]
    float* sden = sm + 38720;     // [128]

    const int c  = blockIdx.x;
    const int bh = blockIdx.y;
    const int b  = bh >> 4, h = bh & 15;
    const int tid = threadIdx.x;
    const int wid = tid >> 5, lane = tid & 31;
    const int g = lane >> 2, tig = lane & 3;

    const size_t rowbase = (size_t)(b * la::SEQ + c * la::CHUNK) * 3072 + h * 64;
    const float* qg = g_qkv + rowbase;
    const float* kg = qg + 1024;
    const float* vg = qg + 2048;

    // stage Q, K featurized (row-major [t][d])
#pragma unroll
    for (int i = 0; i < 4; i++) {
        int idx = i * 256 + tid;
        int t = idx >> 3, d0 = (idx & 7) << 2;
        int n = c * la::CHUNK + t;
        float4 qa = *(const float4*)(qg + (size_t)t * 3072 + d0);
        float4 qb = *(const float4*)(qg + (size_t)t * 3072 + d0 + 32);
        float4 ka = *(const float4*)(kg + (size_t)t * 3072 + d0);
        float4 kb = *(const float4*)(kg + (size_t)t * 3072 + d0 + 32);
        float q1[4] = {qa.x, qa.y, qa.z, qa.w}, q2[4] = {qb.x, qb.y, qb.z, qb.w};
        float k1[4] = {ka.x, ka.y, ka.z, ka.w}, k2[4] = {kb.x, kb.y, kb.z, kb.w};
#pragma unroll
        for (int j = 0; j < 4; j++) {
            float2 cs = g_lut[n * 32 + d0 + j];
            float qo1 = (q1[j] * cs.x - q2[j] * cs.y) * ROPE_SC;
            float qo2 = (q1[j] * cs.y + q2[j] * cs.x) * ROPE_SC;
            sQ[t * 68 + d0 + j]      = tf32f(elu1(qo1));
            sQ[t * 68 + d0 + 32 + j] = tf32f(elu1(qo2));
            float ko1 = (k1[j] * cs.x - k2[j] * cs.y) * ROPE_SC;
            float ko2 = (k1[j] * cs.y + k2[j] * cs.x) * ROPE_SC;
            sK[t * 68 + d0 + j]      = tf32f(elu1(ko1));
            sK[t * 68 + d0 + 32 + j] = tf32f(elu1(ko2));
        }
    }
    // stage KV^T
    const float* kvg = g_ckv + ((size_t)bh * la::NCHUNK + c) * 4096;
#pragma unroll
    for (int i = 0; i < 4; i++) {
        int idx = i * 256 + tid;
        int d = idx >> 4, m0 = (idx & 15) << 2;
        float4 kv4 = *(const float4*)(kvg + d * 64 + m0);
        sKVT[(m0 + 0) * 68 + d] = tf32f(kv4.x);
        sKVT[(m0 + 1) * 68 + d] = tf32f(kv4.y);
        sKVT[(m0 + 2) * 68 + d] = tf32f(kv4.z);
        sKVT[(m0 + 3) * 68 + d] = tf32f(kv4.w);
    }
    if (tid < 64) sks[tid] = g_cks[((size_t)bh * la::NCHUNK + c) * 64 + tid];
    __syncthreads();

    // ---- stage1: S = Qf @ Kf^T  (128x128x64), warp tile 32x64 ----
    {
        const int wm = (wid & 3) * 32, wn = (wid >> 2) * 64;
        const uint32_t* uA = (const uint32_t*)sQ;
        const uint32_t* uB = (const uint32_t*)sK;
        float acc[2][8][4];
#pragma unroll
        for (int mt = 0; mt < 2; mt++)
#pragma unroll
            for (int nt = 0; nt < 8; nt++)
#pragma unroll
                for (int i = 0; i < 4; i++) acc[mt][nt][i] = 0.f;
#pragma unroll
        for (int ks = 0; ks < 8; ks++) {
            const int kb = ks * 8;
            uint32_t af[2][4];
#pragma unroll
            for (int mt = 0; mt < 2; mt++) {
                int r = wm + mt * 16 + g;
                af[mt][0] = uA[r * 68 + kb + tig];
                af[mt][1] = uA[(r + 8) * 68 + kb + tig];
                af[mt][2] = uA[r * 68 + kb + tig + 4];
                af[mt][3] = uA[(r + 8) * 68 + kb + tig + 4];
            }
#pragma unroll
            for (int nt = 0; nt < 8; nt++) {
                int n = wn + nt * 8 + g;
                uint32_t b0 = uB[n * 68 + kb + tig];
                uint32_t b1 = uB[n * 68 + kb + tig + 4];
                MMA_TF32(acc[0][nt], af[0], b0, b1);
                MMA_TF32(acc[1][nt], af[1], b0, b1);
            }
        }
        __syncthreads();  // all warps done reading sK before V overwrites it

        // write masked S (tf32-rounded) to sS
#pragma unroll
        for (int mt = 0; mt < 2; mt++) {
            int r0 = wm + mt * 16 + g, r1 = r0 + 8;
#pragma unroll
            for (int nt = 0; nt < 8; nt++) {
                int j0 = wn + nt * 8 + tig * 2;
                float v00 = (j0     <= r0) ? tf32f(acc[mt][nt][0]) : 0.f;
                float v01 = (j0 + 1 <= r0) ? tf32f(acc[mt][nt][1]) : 0.f;
                float v10 = (j0     <= r1) ? tf32f(acc[mt][nt][2]) : 0.f;
                float v11 = (j0 + 1 <= r1) ? tf32f(acc[mt][nt][3]) : 0.f;
                *(float2*)(sS + r0 * 132 + j0) = make_float2(v00, v01);
                *(float2*)(sS + r1 * 132 + j0) = make_float2(v10, v11);
            }
        }
    }
    // stage V^T into the old sK region
#pragma unroll
    for (int i = 0; i < 8; i++) {
        int idx = i * 256 + tid;
        int t = idx >> 4, m0 = (idx & 15) << 2;
        float4 v4 = *(const float4*)(vg + (size_t)t * 3072 + m0);
        sVT[(m0 + 0) * 132 + t] = tf32f(v4.x);
        sVT[(m0 + 1) * 132 + t] = tf32f(v4.y);
        sVT[(m0 + 2) * 132 + t] = tf32f(v4.z);
        sVT[(m0 + 3) * 132 + t] = tf32f(v4.w);
    }
    __syncthreads();

    // denom per row (fp32): rowsum(masked S) + q . ks_prefix
    if (tid < 128) {
        const int r = tid;
        float s = 0.f;
        for (int j = 0; j < 128; j++) s += sS[r * 132 + j];
        for (int d = 0; d < 64; d++) s = fmaf(sQ[r * 68 + d], sks[d], s);
        sden[r] = fmaxf(s, 1e-6f);
    }
    __syncthreads();

    // ---- stage2: out = S_masked @ V + Qf @ KV^T  (128x64), warp tile 32x32
    {
        const int wm = (wid & 3) * 32, wn = (wid >> 2) * 32;
        const uint32_t* uS = (const uint32_t*)sS;
        const uint32_t* uV = (const uint32_t*)sVT;
        const uint32_t* uQ = (const uint32_t*)sQ;
        const uint32_t* uKV = (const uint32_t*)sKVT;
        float acc[2][4][4];
#pragma unroll
        for (int mt = 0; mt < 2; mt++)
#pragma unroll
            for (int nt = 0; nt < 4; nt++)
#pragma unroll
                for (int i = 0; i < 4; i++) acc[mt][nt][i] = 0.f;

#pragma unroll
        for (int ks = 0; ks < 16; ks++) {
            const int kb = ks * 8;
            uint32_t af[2][4];
#pragma unroll
            for (int mt = 0; mt < 2; mt++) {
                int r = wm + mt * 16 + g;
                af[mt][0] = uS[r * 132 + kb + tig];
                af[mt][1] = uS[(r + 8) * 132 + kb + tig];
                af[mt][2] = uS[r * 132 + kb + tig + 4];
                af[mt][3] = uS[(r + 8) * 132 + kb + tig + 4];
            }
#pragma unroll
            for (int nt = 0; nt < 4; nt++) {
                int n = wn + nt * 8 + g;
                uint32_t b0 = uV[n * 132 + kb + tig];
                uint32_t b1 = uV[n * 132 + kb + tig + 4];
                MMA_TF32(acc[0][nt], af[0], b0, b1);
                MMA_TF32(acc[1][nt], af[1], b0, b1);
            }
        }
#pragma unroll
        for (int ks = 0; ks < 8; ks++) {
            const int kb = ks * 8;
            uint32_t af[2][4];
#pragma unroll
            for (int mt = 0; mt < 2; mt++) {
                int r = wm + mt * 16 + g;
                af[mt][0] = uQ[r * 68 + kb + tig];
                af[mt][1] = uQ[(r + 8) * 68 + kb + tig];
                af[mt][2] = uQ[r * 68 + kb + tig + 4];
                af[mt][3] = uQ[(r + 8) * 68 + kb + tig + 4];
            }
#pragma unroll
            for (int nt = 0; nt < 4; nt++) {
                int n = wn + nt * 8 + g;
                uint32_t b0 = uKV[n * 68 + kb + tig];
                uint32_t b1 = uKV[n * 68 + kb + tig + 4];
                MMA_TF32(acc[0][nt], af[0], b0, b1);
                MMA_TF32(acc[1][nt], af[1], b0, b1);
            }
        }

        // epilogue: divide by denom, store to g_attn
#pragma unroll
        for (int mt = 0; mt < 2; mt++) {
            int r0 = wm + mt * 16 + g, r1 = r0 + 8;
            float inv0 = 1.0f / sden[r0];
            float inv1 = 1.0f / sden[r1];
            float* o0 = g_attn + (size_t)(b * la::SEQ + c * la::CHUNK + r0) * 1024 + h * 64;
            float* o1 = g_attn + (size_t)(b * la::SEQ + c * la::CHUNK + r1) * 1024 + h * 64;
#pragma unroll
            for (int nt = 0; nt < 4; nt++) {
                int m = wn + nt * 8 + tig * 2;
                *(float2*)(o0 + m) = make_float2(acc[mt][nt][0] * inv0, acc[mt][nt][1] * inv0);
                *(float2*)(o1 + m) = make_float2(acc[mt][nt][2] * inv1, acc[mt][nt][3] * inv1);
            }
        }
    }
}

// ---------------- launch ----------------
extern "C" void kernel_launch(void* const* d_in, const int* in_sizes, int n_in,
                              void* d_out, int out_size)
{
    const float* x    = (const float*)d_in[0];
    const float* wqkv = (const float*)d_in[1];
    const float* wout = (const float*)d_in[2];
    float*       out  = (float*)d_out;

    float *qkv, *attn, *wT;
    cudaGetSymbolAddress((void**)&qkv, g_qkv);
    cudaGetSymbolAddress((void**)&attn, g_attn);
    cudaGetSymbolAddress((void**)&wT, g_wT);
    float* wqkvT = wT;
    float* woutT = wT + 3072 * 1024;

    cudaFuncSetAttribute(gemm_mma,   cudaFuncAttributeMaxDynamicSharedMemorySize, GM_SMEM);
    cudaFuncSetAttribute(chunk_sums, cudaFuncAttributeMaxDynamicSharedMemorySize, CS_SMEM);
    cudaFuncSetAttribute(chunk_out,  cudaFuncAttributeMaxDynamicSharedMemorySize, CO_SMEM);

    // 0) rope LUT + weight transposes
    rope_lut_build<<<la::SEQ, 32>>>();
    transpose_w<<<dim3(3072 / 32, 1024 / 32), 256>>>(wqkv, wqkvT, 1024, 3072);
    transpose_w<<<dim3(1024 / 32, 1024 / 32), 256>>>(wout, woutT, 1024, 1024);

    // 1) qkv = x @ w_qkv
    gemm_mma<<<dim3(3072 / 128, la::ROWS / 128), 256, GM_SMEM>>>(x, wqkvT, qkv,
                                                                 la::ROWS, 3072, 1024);

    // 2) per-chunk KV sums (rope+elu fused at load)
    dim3 g3(la::NCHUNK, la::NB * la::NHEADS);
    chunk_sums<<<g3, 256, CS_SMEM>>>();

    // 3) exclusive prefix over chunks
    prefix_scan<<<dim3(la::NB * la::NHEADS, 8), 256>>>();

    // 4) per-chunk outputs (rope+elu fused at load)
    chunk_out<<<g3, 256, CO_SMEM>>>();

    // 5) out = attn @ w_out
    gemm_mma<<<dim3(1024 / 128, la::ROWS / 128), 256, GM_SMEM>>>(attn, woutT, out,
                                                                 la::ROWS, 1024, 1024);
}